// round 9
// baseline (speedup 1.0000x reference)
#include <cuda_runtime.h>
#include <cuda_fp16.h>
#include <cstdint>
#include <math.h>

// -------------------- problem constants --------------------
#define BATCH   8192
#define INSZ    1024
#define HIDSZ   1024
#define KTOT    2048
#define BH      (BATCH * HIDSZ)

// -------------------- GEMM tiling (int8, k in BYTES == elements) ----------
#define BM 128
#define BN 64
#define BK 128                       // 128 int8 k-elements = 128B rows
#define KITERS (KTOT / BK)           // 16
#define RS 144                       // smem row stride bytes (128B data + 16B pad)
#define TILEA (128 * RS)             // 18432 (BM rows)
#define TILEB (64 * RS)              // 9216  (BN rows)
#define STAGE_BYTES (2 * TILEA + 2 * TILEB)   // A1,A2,W1,W2 = 55296
#define SMEM_TOTAL (2 * STAGE_BYTES)          // 110592

// quantization scales
// A = A1/16 + A2/2048 + eps ;  W = W1/4064 + W2/520192 + eps
#define C1 (1.0f / (16.0f * 4064.0f))
#define C2 (C1 / 128.0f)

// -------------------- device scratch --------------------
__device__ __align__(16) int8_t gA1[(size_t)BATCH * KTOT];
__device__ __align__(16) int8_t gA2[(size_t)BATCH * KTOT];
__device__ __align__(16) int8_t gW1[(size_t)3 * HIDSZ * KTOT];   // [g][n][k]
__device__ __align__(16) int8_t gW2[(size_t)3 * HIDSZ * KTOT];
__device__ __align__(16) float  gP [(size_t)3 * BH];             // pre-activations
__device__ __align__(16) float  g_z2[BATCH * 8];

// -------------------- streams/events for graph fork-join --------------------
namespace {
struct GraphStreams {
    cudaStream_t sW = nullptr, sM = nullptr;
    cudaEvent_t evRoot = nullptr, evW = nullptr, evM = nullptr;
    GraphStreams() {
        cudaStreamCreateWithFlags(&sW, cudaStreamNonBlocking);
        cudaStreamCreateWithFlags(&sM, cudaStreamNonBlocking);
        cudaEventCreateWithFlags(&evRoot, cudaEventDisableTiming);
        cudaEventCreateWithFlags(&evW, cudaEventDisableTiming);
        cudaEventCreateWithFlags(&evM, cudaEventDisableTiming);
    }
};
GraphStreams g_gs;
}

// -------------------- helpers --------------------
__device__ __forceinline__ uint32_t smem_u32(const void* p) {
    uint32_t a;
    asm("{ .reg .u64 t; cvta.to.shared.u64 t, %1; cvt.u32.u64 %0, t; }" : "=r"(a) : "l"(p));
    return a;
}
#define CPASYNC16(dst, src) \
    asm volatile("cp.async.cg.shared.global [%0], [%1], 16;" :: "r"(dst), "l"(src))
#define CP_COMMIT() asm volatile("cp.async.commit_group;")
#define CP_WAIT0()  asm volatile("cp.async.wait_group 0;")

__device__ __forceinline__ void ldmx4(uint32_t addr, uint32_t& r0, uint32_t& r1,
                                      uint32_t& r2, uint32_t& r3) {
    asm volatile("ldmatrix.sync.aligned.m8n8.x4.shared.b16 {%0,%1,%2,%3}, [%4];"
                 : "=r"(r0), "=r"(r1), "=r"(r2), "=r"(r3) : "r"(addr));
}
__device__ __forceinline__ void mma16832s8(int* d, const uint32_t* a, const uint32_t* b) {
    asm volatile(
        "mma.sync.aligned.m16n8k32.row.col.s32.s8.s8.s32 "
        "{%0,%1,%2,%3}, {%4,%5,%6,%7}, {%8,%9}, {%0,%1,%2,%3};"
        : "+r"(d[0]), "+r"(d[1]), "+r"(d[2]), "+r"(d[3])
        : "r"(a[0]), "r"(a[1]), "r"(a[2]), "r"(a[3]), "r"(b[0]), "r"(b[1]));
}

// well-defined float -> int8 quantization (aarch64-safe: never float->char)
__device__ __forceinline__ int8_t q8(float v) {
    int i = (int)rintf(v);
    i = min(max(i, -127), 127);
    return (int8_t)i;
}

__device__ __forceinline__ float sigm(float x) { return 1.0f / (1.0f + __expf(-x)); }
__device__ __forceinline__ float tanh_(float x) {
    float t = __expf(2.0f * x);
    return 1.0f - 2.0f / (t + 1.0f);
}

// ---------------------------------------------------------------------------
// convert A = concat(x, h) -> 2-term int8 split
// ---------------------------------------------------------------------------
__global__ void convA(const float* __restrict__ x, const float* __restrict__ h) {
    int idx = blockIdx.x * blockDim.x + threadIdx.x;   // float4 index
    int row = idx >> 9;                                 // KTOT/4 = 512
    int k   = (idx & 511) * 4;
    float4 v = (k < INSZ)
        ? *(const float4*)(x + (size_t)row * INSZ + k)
        : *(const float4*)(h + (size_t)row * HIDSZ + (k - INSZ));
    float a[4] = {v.x, v.y, v.z, v.w};
    int8_t q1[4], q2[4];
#pragma unroll
    for (int i = 0; i < 4; i++) {
        q1[i] = q8(a[i] * 16.0f);
        float r = a[i] - (float)q1[i] * (1.0f / 16.0f);
        q2[i] = q8(r * 2048.0f);
    }
    size_t o = (size_t)row * KTOT + k;
    uint32_t p1, p2;
    memcpy(&p1, q1, 4); memcpy(&p2, q2, 4);
    *(uint32_t*)(gA1 + o) = p1;
    *(uint32_t*)(gA2 + o) = p2;
}

// ---------------------------------------------------------------------------
// transpose + 2-term int8 split of weights: gW[g][n][k] = W[k][n]
// |W| <= 1/32 exactly (uniform init), so sW = 4064 fits s8 with no clamp.
// ---------------------------------------------------------------------------
__global__ void convW(const float* __restrict__ Wxi, const float* __restrict__ Whi,
                      const float* __restrict__ Wxc, const float* __restrict__ Whc,
                      const float* __restrict__ Wxo, const float* __restrict__ Who) {
    __shared__ float t[32][33];
    int mat = blockIdx.z;
    const float* src;
    switch (mat) {
        case 0: src = Wxi; break; case 1: src = Whi; break;
        case 2: src = Wxc; break; case 3: src = Whc; break;
        case 4: src = Wxo; break; default: src = Who; break;
    }
    int n0 = blockIdx.x * 32, k0 = blockIdx.y * 32;
    int tx = threadIdx.x, ty = threadIdx.y;   // 32 x 8
#pragma unroll
    for (int j = 0; j < 4; j++)
        t[ty + j * 8][tx] = src[(size_t)(k0 + ty + j * 8) * HIDSZ + n0 + tx];
    __syncthreads();
    int g = mat >> 1, half = mat & 1;
#pragma unroll
    for (int j = 0; j < 4; j++) {
        int n = n0 + ty + j * 8, k = k0 + tx;
        float w = t[tx][ty + j * 8];
        int8_t w1 = q8(w * 4064.0f);
        float rw = w - (float)w1 * (1.0f / 4064.0f);
        int8_t w2 = q8(rw * 520192.0f);             // 4064*128
        size_t o = ((size_t)(g * HIDSZ + n)) * KTOT + half * INSZ + k;
        gW1[o] = w1;
        gW2[o] = w2;
    }
}

// ---------------------------------------------------------------------------
// forget-gate MLP front half: z2 = relu(relu(xh@W1+b1)@W2+b2)
// ---------------------------------------------------------------------------
__global__ void mlp_kernel(const float* __restrict__ x, const float* __restrict__ h,
                           const float* __restrict__ W1, const float* __restrict__ b1,
                           const float* __restrict__ W2, const float* __restrict__ b2)
{
    extern __shared__ float sW1T[];   // [16][2048]
    const int tid = threadIdx.x;
    for (int i = tid; i < KTOT * 16; i += blockDim.x) {
        int k = i >> 4, j = i & 15;
        sW1T[j * KTOT + k] = W1[i];
    }
    __syncthreads();

    const int warp = tid >> 5, lane = tid & 31;
    const int gw = blockIdx.x * (blockDim.x >> 5) + warp;
    const int nw = gridDim.x * (blockDim.x >> 5);

    float b1r[16];
#pragma unroll
    for (int j = 0; j < 16; j++) b1r[j] = b1[j];
    float w2r[16];
    float b2r = 0.0f;
    if (lane < 8) {
        b2r = b2[lane];
#pragma unroll
        for (int j = 0; j < 16; j++) w2r[j] = W2[j * 8 + lane];
    }

    for (int row = gw; row < BATCH; row += nw) {
        const float* xr = x + (size_t)row * INSZ;
        const float* hr = h + (size_t)row * HIDSZ;
        float acc[16];
#pragma unroll
        for (int j = 0; j < 16; j++) acc[j] = 0.0f;
#pragma unroll 4
        for (int k = lane; k < KTOT; k += 32) {
            float v = (k < INSZ) ? xr[k] : hr[k - INSZ];
#pragma unroll
            for (int j = 0; j < 16; j++)
                acc[j] = fmaf(v, sW1T[j * KTOT + k], acc[j]);
        }
#pragma unroll
        for (int off = 16; off; off >>= 1) {
#pragma unroll
            for (int j = 0; j < 16; j++)
                acc[j] += __shfl_xor_sync(0xffffffffu, acc[j], off);
        }
        if (lane < 8) {
            float s = b2r;
#pragma unroll
            for (int j = 0; j < 16; j++)
                s = fmaf(fmaxf(acc[j] + b1r[j], 0.0f), w2r[j], s);
            g_z2[row * 8 + lane] = fmaxf(s, 0.0f);
        }
    }
}

// ---------------------------------------------------------------------------
// IMMA GEMM: P[g] = A @ W[g]^T, 3 int8 terms (A1W1; A1W2+A2W1)
// grid (n 16, m 64, gate 3), 256 threads, warp grid 4(m) x 2(n), warp 32x32
// ---------------------------------------------------------------------------
__global__ __launch_bounds__(256, 2)
void gemm_imma(float* __restrict__ dummy)
{
    extern __shared__ char smem[];
    const uint32_t sbase = smem_u32(smem);

    const int tid = threadIdx.x;
    const int wid = tid >> 5, lane = tid & 31;
    const int wm = wid & 3, wn = wid >> 2;          // warp coords: 4(m) x 2(n)
    const int g  = blockIdx.z;
    const int m0 = blockIdx.y * BM;
    const int n0 = blockIdx.x * BN;

    const int8_t* A1 = gA1 + (size_t)m0 * KTOT;
    const int8_t* A2 = gA2 + (size_t)m0 * KTOT;
    const int8_t* B1 = gW1 + ((size_t)g * HIDSZ + n0) * KTOT;
    const int8_t* B2 = gW2 + ((size_t)g * HIDSZ + n0) * KTOT;

    // staged copy: A1,A2 (128 rows x 128B) + W1,W2 (64 rows x 128B)
    auto copy_stage = [&](int kt, int s) {
        const uint32_t base = sbase + s * STAGE_BYTES;
        const int koff = kt * BK;
#pragma unroll
        for (int i = tid; i < 1024; i += 256) {
            int row = i >> 3, ch = i & 7;
            uint32_t d = base + row * RS + ch * 16;
            CPASYNC16(d,         A1 + (size_t)row * KTOT + koff + ch * 16);
            CPASYNC16(d + TILEA, A2 + (size_t)row * KTOT + koff + ch * 16);
        }
#pragma unroll
        for (int i = tid; i < 512; i += 256) {
            int row = i >> 3, ch = i & 7;
            uint32_t d = base + 2 * TILEA + row * RS + ch * 16;
            CPASYNC16(d,         B1 + (size_t)row * KTOT + koff + ch * 16);
            CPASYNC16(d + TILEB, B2 + (size_t)row * KTOT + koff + ch * 16);
        }
    };

    int acc1[2][4][4], acc2[2][4][4];
#pragma unroll
    for (int mt = 0; mt < 2; mt++)
#pragma unroll
        for (int nt = 0; nt < 4; nt++)
#pragma unroll
            for (int r = 0; r < 4; r++) { acc1[mt][nt][r] = 0; acc2[mt][nt][r] = 0; }

    // ldmatrix address components (byte-identical to fp16-k16 layout)
    const uint32_t aRowOff = (uint32_t)((wm * 32 + (lane & 15)) * RS + ((lane >> 4) & 1) * 16);
    const uint32_t bRowOff = (uint32_t)((wn * 32 + (lane & 7) + ((lane >> 4) & 1) * 8) * RS
                                        + ((lane >> 3) & 1) * 16);

    copy_stage(0, 0);
    CP_COMMIT();

    for (int kt = 0; kt < KITERS; kt++) {
        const int s = kt & 1;
        CP_WAIT0();
        __syncthreads();
        if (kt + 1 < KITERS) { copy_stage(kt + 1, s ^ 1); CP_COMMIT(); }

        const uint32_t base = sbase + s * STAGE_BYTES;
        const uint32_t aB = base + aRowOff;
        const uint32_t bB = base + 2 * TILEA + bRowOff;

#pragma unroll
        for (int ks = 0; ks < 4; ks++) {
            const uint32_t kb = (uint32_t)(ks * 32);
            uint32_t b1[8], b2[8];
            ldmx4(bB + kb,                 b1[0], b1[1], b1[2], b1[3]);   // W1 nt 0,1
            ldmx4(bB + 16 * RS + kb,       b1[4], b1[5], b1[6], b1[7]);   // W1 nt 2,3
            ldmx4(bB + TILEB + kb,         b2[0], b2[1], b2[2], b2[3]);   // W2 nt 0,1
            ldmx4(bB + TILEB + 16*RS + kb, b2[4], b2[5], b2[6], b2[7]);   // W2 nt 2,3

            uint32_t a1[2][4], a2[2][4];
#pragma unroll
            for (int mt = 0; mt < 2; mt++) {
                ldmx4(aB + mt * 16 * RS + kb,         a1[mt][0], a1[mt][1], a1[mt][2], a1[mt][3]);
                ldmx4(aB + TILEA + mt * 16 * RS + kb, a2[mt][0], a2[mt][1], a2[mt][2], a2[mt][3]);
            }
#pragma unroll
            for (int mt = 0; mt < 2; mt++)
#pragma unroll
                for (int nt = 0; nt < 4; nt++) {
                    mma16832s8(acc1[mt][nt], a1[mt], &b1[nt * 2]);   // A1*W1
                    mma16832s8(acc2[mt][nt], a1[mt], &b2[nt * 2]);   // A1*W2
                    mma16832s8(acc2[mt][nt], a2[mt], &b1[nt * 2]);   // A2*W1
                }
        }
        __syncthreads();
    }

    // dequant + write pre-activations
    float* P = gP + (size_t)g * BH;
    const int rbase = m0 + wm * 32 + (lane >> 2);
    const int cbase = n0 + wn * 32 + (lane & 3) * 2;
#pragma unroll
    for (int mt = 0; mt < 2; mt++)
#pragma unroll
        for (int nt = 0; nt < 4; nt++) {
            float v0 = C1 * (float)acc1[mt][nt][0] + C2 * (float)acc2[mt][nt][0];
            float v1 = C1 * (float)acc1[mt][nt][1] + C2 * (float)acc2[mt][nt][1];
            float v2 = C1 * (float)acc1[mt][nt][2] + C2 * (float)acc2[mt][nt][2];
            float v3 = C1 * (float)acc1[mt][nt][3] + C2 * (float)acc2[mt][nt][3];
            size_t o0 = (size_t)(rbase + mt * 16) * HIDSZ + cbase + nt * 8;
            *(float2*)&P[o0]             = make_float2(v0, v1);
            *(float2*)&P[o0 + 8 * HIDSZ] = make_float2(v2, v3);
        }
}

// ---------------------------------------------------------------------------
// epilogue: activations + forget-MLP tail + LSTM update.  8 rows per block.
// ---------------------------------------------------------------------------
__global__ __launch_bounds__(256)
void epilogue(const float* __restrict__ c,
              const float* __restrict__ b_i, const float* __restrict__ b_c,
              const float* __restrict__ b_o,
              const float* __restrict__ W3, const float* __restrict__ b3,
              float* __restrict__ out)
{
    const int r0 = blockIdx.x * 8;
    const int col = threadIdx.x * 4;
    __shared__ float z2s[8][8];
    if (threadIdx.x < 64)
        z2s[threadIdx.x >> 3][threadIdx.x & 7] =
            g_z2[(r0 + (threadIdx.x >> 3)) * 8 + (threadIdx.x & 7)];
    __syncthreads();

    float4 bi = *(const float4*)&b_i[col];
    float4 bc = *(const float4*)&b_c[col];
    float4 bo = *(const float4*)&b_o[col];
    float4 b3v = *(const float4*)&b3[col];
    float4 w3[8];
#pragma unroll
    for (int q = 0; q < 8; q++) w3[q] = *(const float4*)&W3[q * HIDSZ + col];

#pragma unroll 1
    for (int rr = 0; rr < 8; rr++) {
        const int row = r0 + rr;
        const size_t base = (size_t)row * HIDSZ + col;
        float4 pi = *(const float4*)&gP[base];
        float4 pc = *(const float4*)&gP[BH + base];
        float4 po = *(const float4*)&gP[2 * (size_t)BH + base];
        float4 cv = *(const float4*)&c[base];
        float piA[4] = {pi.x, pi.y, pi.z, pi.w};
        float pcA[4] = {pc.x, pc.y, pc.z, pc.w};
        float poA[4] = {po.x, po.y, po.z, po.w};
        float cA[4]  = {cv.x, cv.y, cv.z, cv.w};
        float biA[4] = {bi.x, bi.y, bi.z, bi.w};
        float bcA[4] = {bc.x, bc.y, bc.z, bc.w};
        float boA[4] = {bo.x, bo.y, bo.z, bo.w};
        float b3A[4] = {b3v.x, b3v.y, b3v.z, b3v.w};

        float hn[4], cn[4], fv[4];
#pragma unroll
        for (int j = 0; j < 4; j++) {
            float ii = sigm(piA[j] + biA[j]);
            float gg = tanh_(pcA[j] + bcA[j]);
            float oo = sigm(poA[j] + boA[j]);
            float sf = b3A[j];
#pragma unroll
            for (int q = 0; q < 8; q++) {
                const float* wq = (const float*)&w3[q];
                sf = fmaf(z2s[rr][q], wq[j], sf);
            }
            float ff = sigm(sf);
            float cN = fmaf(ff, cA[j], ii * gg);
            hn[j] = oo * tanh_(cN);
            cn[j] = cN;
            fv[j] = ff;
        }
        *(float4*)&out[base]              = make_float4(hn[0], hn[1], hn[2], hn[3]);
        *(float4*)&out[BH + base]         = make_float4(cn[0], cn[1], cn[2], cn[3]);
        *(float4*)&out[2 * (size_t)BH + base] = make_float4(fv[0], fv[1], fv[2], fv[3]);
    }
}

// ---------------------------------------------------------------------------
extern "C" void kernel_launch(void* const* d_in, const int* in_sizes, int n_in,
                              void* d_out, int out_size)
{
    const float* x    = (const float*)d_in[0];
    const float* h    = (const float*)d_in[1];
    const float* c    = (const float*)d_in[2];
    const float* W_hi = (const float*)d_in[3];
    const float* W_xi = (const float*)d_in[4];
    const float* b_i  = (const float*)d_in[5];
    const float* W_hc = (const float*)d_in[6];
    const float* W_xc = (const float*)d_in[7];
    const float* b_c  = (const float*)d_in[8];
    const float* W_ho = (const float*)d_in[9];
    const float* W_xo = (const float*)d_in[10];
    const float* b_o  = (const float*)d_in[11];
    const float* W1   = (const float*)d_in[12];
    const float* b1   = (const float*)d_in[13];
    const float* W2   = (const float*)d_in[14];
    const float* b2   = (const float*)d_in[15];
    const float* W3   = (const float*)d_in[16];
    const float* b3   = (const float*)d_in[17];
    float* out = (float*)d_out;

    cudaFuncSetAttribute(mlp_kernel, cudaFuncAttributeMaxDynamicSharedMemorySize,
                         16 * KTOT * (int)sizeof(float));
    cudaFuncSetAttribute(gemm_imma, cudaFuncAttributeMaxDynamicSharedMemorySize,
                         SMEM_TOTAL);

    // fork: convA on main stream; convW and mlp on side streams
    cudaEventRecord(g_gs.evRoot, 0);
    cudaStreamWaitEvent(g_gs.sW, g_gs.evRoot, 0);
    cudaStreamWaitEvent(g_gs.sM, g_gs.evRoot, 0);

    convA<<<(BATCH * KTOT / 4) / 256, 256>>>(x, h);
    convW<<<dim3(32, 32, 6), dim3(32, 8), 0, g_gs.sW>>>(W_xi, W_hi, W_xc, W_hc, W_xo, W_ho);
    mlp_kernel<<<256, 256, 16 * KTOT * sizeof(float), g_gs.sM>>>(x, h, W1, b1, W2, b2);

    // gemm needs convA (same stream) + convW (join sW)
    cudaEventRecord(g_gs.evW, g_gs.sW);
    cudaStreamWaitEvent(0, g_gs.evW, 0);

    dim3 grid(HIDSZ / BN, BATCH / BM, 3);   // (16, 64, 3)
    gemm_imma<<<grid, 256, SMEM_TOTAL>>>(nullptr);

    // epilogue needs gemm (same stream) + mlp (join sM)
    cudaEventRecord(g_gs.evM, g_gs.sM);
    cudaStreamWaitEvent(0, g_gs.evM, 0);

    epilogue<<<BATCH / 8, 256>>>(c, b_i, b_c, b_o, W3, b3, out);
}

// round 10
// speedup vs baseline: 3.0425x; 3.0425x over previous
#include <cuda_runtime.h>
#include <cuda_fp16.h>
#include <cstdint>
#include <math.h>

// -------------------- problem constants --------------------
#define BATCH   8192
#define INSZ    1024
#define HIDSZ   1024
#define KTOT    2048
#define BH      (BATCH * HIDSZ)

// -------------------- GEMM tiling --------------------
#define BM 64
#define BN 128
#define BK 64
#define KITERS (KTOT / BK)          // 32
#define RS 144                      // smem row stride bytes (128B data + 16B pad)
#define TILEA (64 * RS)             // 9216  (A hi or lo, BM rows)
#define TILEB (128 * RS)            // 18432 (B, BN rows)
#define STAGE_BYTES (2 * TILEA + TILEB)   // 36864
#define SMEM_TOTAL (2 * STAGE_BYTES)      // 73728  (3 CTAs/SM: 221KB)

// -------------------- device scratch --------------------
__device__ __align__(16) __half gAh[(size_t)BATCH * KTOT];       // A hi (fp16)
__device__ __align__(16) __half gAl[(size_t)BATCH * KTOT];       // A lo (fp16)
__device__ __align__(16) __half gW [(size_t)3 * HIDSZ * KTOT];   // W^T: [g][n][k]
__device__ __align__(16) float  gP [(size_t)3 * BH];             // pre-activations
__device__ __align__(16) float  g_z2[BATCH * 8];

// -------------------- streams/events for graph fork-join --------------------
namespace {
struct GraphStreams {
    cudaStream_t sW = nullptr, sM = nullptr;
    cudaEvent_t evRoot = nullptr, evW = nullptr, evM = nullptr;
    GraphStreams() {
        cudaStreamCreateWithFlags(&sW, cudaStreamNonBlocking);
        cudaStreamCreateWithFlags(&sM, cudaStreamNonBlocking);
        cudaEventCreateWithFlags(&evRoot, cudaEventDisableTiming);
        cudaEventCreateWithFlags(&evW, cudaEventDisableTiming);
        cudaEventCreateWithFlags(&evM, cudaEventDisableTiming);
    }
};
GraphStreams g_gs;
}

// -------------------- helpers --------------------
__device__ __forceinline__ uint32_t smem_u32(const void* p) {
    uint32_t a;
    asm("{ .reg .u64 t; cvta.to.shared.u64 t, %1; cvt.u32.u64 %0, t; }" : "=r"(a) : "l"(p));
    return a;
}
#define CPASYNC16(dst, src) \
    asm volatile("cp.async.cg.shared.global [%0], [%1], 16;" :: "r"(dst), "l"(src))
#define CP_COMMIT() asm volatile("cp.async.commit_group;")
#define CP_WAIT0()  asm volatile("cp.async.wait_group 0;")

__device__ __forceinline__ void ldmx4(uint32_t addr, uint32_t& r0, uint32_t& r1,
                                      uint32_t& r2, uint32_t& r3) {
    asm volatile("ldmatrix.sync.aligned.m8n8.x4.shared.b16 {%0,%1,%2,%3}, [%4];"
                 : "=r"(r0), "=r"(r1), "=r"(r2), "=r"(r3) : "r"(addr));
}
__device__ __forceinline__ void mma16816(float* d, const uint32_t* a, const uint32_t* b) {
    asm volatile(
        "mma.sync.aligned.m16n8k16.row.col.f32.f16.f16.f32 "
        "{%0,%1,%2,%3}, {%4,%5,%6,%7}, {%8,%9}, {%0,%1,%2,%3};"
        : "+f"(d[0]), "+f"(d[1]), "+f"(d[2]), "+f"(d[3])
        : "r"(a[0]), "r"(a[1]), "r"(a[2]), "r"(a[3]), "r"(b[0]), "r"(b[1]));
}

__device__ __forceinline__ float sigm(float x) { return 1.0f / (1.0f + __expf(-x)); }
__device__ __forceinline__ float tanh_(float x) {
    float t = __expf(2.0f * x);
    return 1.0f - 2.0f / (t + 1.0f);
}

// ---------------------------------------------------------------------------
// convert A = concat(x, h) -> fp16 hi/lo split
// ---------------------------------------------------------------------------
__global__ void convA(const float* __restrict__ x, const float* __restrict__ h) {
    int idx = blockIdx.x * blockDim.x + threadIdx.x;   // float4 index
    int row = idx >> 9;                                 // KTOT/4 = 512
    int k   = (idx & 511) * 4;
    float4 v = (k < INSZ)
        ? *(const float4*)(x + (size_t)row * INSZ + k)
        : *(const float4*)(h + (size_t)row * HIDSZ + (k - INSZ));
    float a[4] = {v.x, v.y, v.z, v.w};
    __half hi[4], lo[4];
#pragma unroll
    for (int i = 0; i < 4; i++) {
        hi[i] = __float2half_rn(a[i]);
        lo[i] = __float2half_rn(a[i] - __half2float(hi[i]));
    }
    size_t o = (size_t)row * KTOT + k;
    __half2* dh = (__half2*)(gAh + o);
    __half2* dl = (__half2*)(gAl + o);
    dh[0] = __halves2half2(hi[0], hi[1]); dh[1] = __halves2half2(hi[2], hi[3]);
    dl[0] = __halves2half2(lo[0], lo[1]); dl[1] = __halves2half2(lo[2], lo[3]);
}

// ---------------------------------------------------------------------------
// transpose weights: gW[g][n][k] = W[k][n]   (mat = g*2 + half, half0=Wx,1=Wh)
// ---------------------------------------------------------------------------
__global__ void convW(const float* __restrict__ Wxi, const float* __restrict__ Whi,
                      const float* __restrict__ Wxc, const float* __restrict__ Whc,
                      const float* __restrict__ Wxo, const float* __restrict__ Who) {
    __shared__ float t[32][33];
    int mat = blockIdx.z;
    const float* src;
    switch (mat) {
        case 0: src = Wxi; break; case 1: src = Whi; break;
        case 2: src = Wxc; break; case 3: src = Whc; break;
        case 4: src = Wxo; break; default: src = Who; break;
    }
    int n0 = blockIdx.x * 32, k0 = blockIdx.y * 32;
    int tx = threadIdx.x, ty = threadIdx.y;   // 32 x 8
#pragma unroll
    for (int j = 0; j < 4; j++)
        t[ty + j * 8][tx] = src[(size_t)(k0 + ty + j * 8) * HIDSZ + n0 + tx];
    __syncthreads();
    int g = mat >> 1, half = mat & 1;
#pragma unroll
    for (int j = 0; j < 4; j++) {
        int n = n0 + ty + j * 8, k = k0 + tx;
        size_t o = ((size_t)(g * HIDSZ + n)) * KTOT + half * INSZ + k;
        gW[o] = __float2half_rn(t[tx][ty + j * 8]);
    }
}

// ---------------------------------------------------------------------------
// forget-gate MLP front half: z2 = relu(relu(xh@W1+b1)@W2+b2)
// ---------------------------------------------------------------------------
__global__ void mlp_kernel(const float* __restrict__ x, const float* __restrict__ h,
                           const float* __restrict__ W1, const float* __restrict__ b1,
                           const float* __restrict__ W2, const float* __restrict__ b2)
{
    extern __shared__ float sW1T[];   // [16][2048]
    const int tid = threadIdx.x;
    for (int i = tid; i < KTOT * 16; i += blockDim.x) {
        int k = i >> 4, j = i & 15;
        sW1T[j * KTOT + k] = W1[i];
    }
    __syncthreads();

    const int warp = tid >> 5, lane = tid & 31;
    const int gw = blockIdx.x * (blockDim.x >> 5) + warp;
    const int nw = gridDim.x * (blockDim.x >> 5);

    float b1r[16];
#pragma unroll
    for (int j = 0; j < 16; j++) b1r[j] = b1[j];
    float w2r[16];
    float b2r = 0.0f;
    if (lane < 8) {
        b2r = b2[lane];
#pragma unroll
        for (int j = 0; j < 16; j++) w2r[j] = W2[j * 8 + lane];
    }

    for (int row = gw; row < BATCH; row += nw) {
        const float* xr = x + (size_t)row * INSZ;
        const float* hr = h + (size_t)row * HIDSZ;
        float acc[16];
#pragma unroll
        for (int j = 0; j < 16; j++) acc[j] = 0.0f;
#pragma unroll 4
        for (int k = lane; k < KTOT; k += 32) {
            float v = (k < INSZ) ? xr[k] : hr[k - INSZ];
#pragma unroll
            for (int j = 0; j < 16; j++)
                acc[j] = fmaf(v, sW1T[j * KTOT + k], acc[j]);
        }
#pragma unroll
        for (int off = 16; off; off >>= 1) {
#pragma unroll
            for (int j = 0; j < 16; j++)
                acc[j] += __shfl_xor_sync(0xffffffffu, acc[j], off);
        }
        if (lane < 8) {
            float s = b2r;
#pragma unroll
            for (int j = 0; j < 16; j++)
                s = fmaf(fmaxf(acc[j] + b1r[j], 0.0f), w2r[j], s);
            g_z2[row * 8 + lane] = fmaxf(s, 0.0f);
        }
    }
}

// ---------------------------------------------------------------------------
// HMMA GEMM: P[g] = A @ W[g]^T  (2-term fp16 split of A)
// grid (n 8, m 128, gate 3), 256 threads, warp grid 2(m) x 4(n), warp tile 32x32
// 3 CTAs/SM (24 warps): small warp tile (32 acc regs) to fit 85-reg budget
// ---------------------------------------------------------------------------
__global__ __launch_bounds__(256, 3)
void gemm_hmma(float* __restrict__ dummy)
{
    extern __shared__ char smem[];
    const uint32_t sbase = smem_u32(smem);

    const int tid = threadIdx.x;
    const int wid = tid >> 5, lane = tid & 31;
    const int wm = wid & 1, wn = wid >> 1;          // warp coords: 2(m) x 4(n)
    const int g  = blockIdx.z;
    const int m0 = blockIdx.y * BM;
    const int n0 = blockIdx.x * BN;

    const __half* Ah = gAh + (size_t)m0 * KTOT;
    const __half* Al = gAl + (size_t)m0 * KTOT;
    const __half* Bp = gW + ((size_t)g * HIDSZ + n0) * KTOT;

    // staged copy: A hi/lo (64 rows x 128B) + B (128 rows x 128B)
    auto copy_stage = [&](int kt, int s) {
        const uint32_t base = sbase + s * STAGE_BYTES;
        const int koff = kt * BK;
#pragma unroll
        for (int i = tid; i < 512; i += 256) {
            int row = i >> 3, ch = i & 7;
            uint32_t d = base + row * RS + ch * 16;
            CPASYNC16(d,         Ah + (size_t)row * KTOT + koff + ch * 8);
            CPASYNC16(d + TILEA, Al + (size_t)row * KTOT + koff + ch * 8);
        }
#pragma unroll
        for (int i = tid; i < 1024; i += 256) {
            int row = i >> 3, ch = i & 7;
            uint32_t d = base + 2 * TILEA + row * RS + ch * 16;
            CPASYNC16(d, Bp + (size_t)row * KTOT + koff + ch * 8);
        }
    };

    float acc[2][4][4];
#pragma unroll
    for (int mt = 0; mt < 2; mt++)
#pragma unroll
        for (int nt = 0; nt < 4; nt++)
#pragma unroll
            for (int r = 0; r < 4; r++) acc[mt][nt][r] = 0.0f;

    // ldmatrix address components (within a stage, before k-step offset)
    // A: rows = wm*32 + mt*16 + (lane&15); col16 = ((lane>>4)&1)*16
    const uint32_t aRowOff = (uint32_t)((wm * 32 + (lane & 15)) * RS + ((lane >> 4) & 1) * 16);
    // B: rows = wn*32 + ntpair*16 + (lane&7) + ((lane>>4)&1)*8; col16 = ((lane>>3)&1)*16
    const uint32_t bRowOff = (uint32_t)((wn * 32 + (lane & 7) + ((lane >> 4) & 1) * 8) * RS
                                        + ((lane >> 3) & 1) * 16);

    copy_stage(0, 0);
    CP_COMMIT();

    for (int kt = 0; kt < KITERS; kt++) {
        const int s = kt & 1;
        CP_WAIT0();
        __syncthreads();
        if (kt + 1 < KITERS) { copy_stage(kt + 1, s ^ 1); CP_COMMIT(); }

        const uint32_t base = sbase + s * STAGE_BYTES;
        const uint32_t aB = base + aRowOff;
        const uint32_t bB = base + 2 * TILEA + bRowOff;

#pragma unroll
        for (int ks = 0; ks < 4; ks++) {
            const uint32_t kb = (uint32_t)(ks * 32);
            uint32_t b[8];
            ldmx4(bB + kb,            b[0], b[1], b[2], b[3]);   // nt 0,1
            ldmx4(bB + 16 * RS + kb,  b[4], b[5], b[6], b[7]);   // nt 2,3

            uint32_t a[2][4];                                    // reused hi then lo
#pragma unroll
            for (int mt = 0; mt < 2; mt++)
                ldmx4(aB + mt * 16 * RS + kb, a[mt][0], a[mt][1], a[mt][2], a[mt][3]);
#pragma unroll
            for (int mt = 0; mt < 2; mt++)
#pragma unroll
                for (int nt = 0; nt < 4; nt++)
                    mma16816(acc[mt][nt], a[mt], &b[nt * 2]);

#pragma unroll
            for (int mt = 0; mt < 2; mt++)
                ldmx4(aB + TILEA + mt * 16 * RS + kb,
                      a[mt][0], a[mt][1], a[mt][2], a[mt][3]);
#pragma unroll
            for (int mt = 0; mt < 2; mt++)
#pragma unroll
                for (int nt = 0; nt < 4; nt++)
                    mma16816(acc[mt][nt], a[mt], &b[nt * 2]);
        }
        __syncthreads();
    }

    // write pre-activations
    float* P = gP + (size_t)g * BH;
    const int rbase = m0 + wm * 32 + (lane >> 2);
    const int cbase = n0 + wn * 32 + (lane & 3) * 2;
#pragma unroll
    for (int mt = 0; mt < 2; mt++)
#pragma unroll
        for (int nt = 0; nt < 4; nt++) {
            size_t o0 = (size_t)(rbase + mt * 16) * HIDSZ + cbase + nt * 8;
            *(float2*)&P[o0]             = make_float2(acc[mt][nt][0], acc[mt][nt][1]);
            *(float2*)&P[o0 + 8 * HIDSZ] = make_float2(acc[mt][nt][2], acc[mt][nt][3]);
        }
}

// ---------------------------------------------------------------------------
// epilogue: activations + forget-MLP tail + LSTM update.  8 rows per block.
// ---------------------------------------------------------------------------
__global__ __launch_bounds__(256)
void epilogue(const float* __restrict__ c,
              const float* __restrict__ b_i, const float* __restrict__ b_c,
              const float* __restrict__ b_o,
              const float* __restrict__ W3, const float* __restrict__ b3,
              float* __restrict__ out)
{
    const int r0 = blockIdx.x * 8;
    const int col = threadIdx.x * 4;
    __shared__ float z2s[8][8];
    if (threadIdx.x < 64)
        z2s[threadIdx.x >> 3][threadIdx.x & 7] =
            g_z2[(r0 + (threadIdx.x >> 3)) * 8 + (threadIdx.x & 7)];
    __syncthreads();

    float4 bi = *(const float4*)&b_i[col];
    float4 bc = *(const float4*)&b_c[col];
    float4 bo = *(const float4*)&b_o[col];
    float4 b3v = *(const float4*)&b3[col];
    float4 w3[8];
#pragma unroll
    for (int q = 0; q < 8; q++) w3[q] = *(const float4*)&W3[q * HIDSZ + col];

#pragma unroll 1
    for (int rr = 0; rr < 8; rr++) {
        const int row = r0 + rr;
        const size_t base = (size_t)row * HIDSZ + col;
        float4 pi = *(const float4*)&gP[base];
        float4 pc = *(const float4*)&gP[BH + base];
        float4 po = *(const float4*)&gP[2 * (size_t)BH + base];
        float4 cv = *(const float4*)&c[base];
        float piA[4] = {pi.x, pi.y, pi.z, pi.w};
        float pcA[4] = {pc.x, pc.y, pc.z, pc.w};
        float poA[4] = {po.x, po.y, po.z, po.w};
        float cA[4]  = {cv.x, cv.y, cv.z, cv.w};
        float biA[4] = {bi.x, bi.y, bi.z, bi.w};
        float bcA[4] = {bc.x, bc.y, bc.z, bc.w};
        float boA[4] = {bo.x, bo.y, bo.z, bo.w};
        float b3A[4] = {b3v.x, b3v.y, b3v.z, b3v.w};

        float hn[4], cn[4], fv[4];
#pragma unroll
        for (int j = 0; j < 4; j++) {
            float ii = sigm(piA[j] + biA[j]);
            float gg = tanh_(pcA[j] + bcA[j]);
            float oo = sigm(poA[j] + boA[j]);
            float sf = b3A[j];
#pragma unroll
            for (int q = 0; q < 8; q++) {
                const float* wq = (const float*)&w3[q];
                sf = fmaf(z2s[rr][q], wq[j], sf);
            }
            float ff = sigm(sf);
            float cN = fmaf(ff, cA[j], ii * gg);
            hn[j] = oo * tanh_(cN);
            cn[j] = cN;
            fv[j] = ff;
        }
        *(float4*)&out[base]              = make_float4(hn[0], hn[1], hn[2], hn[3]);
        *(float4*)&out[BH + base]         = make_float4(cn[0], cn[1], cn[2], cn[3]);
        *(float4*)&out[2 * (size_t)BH + base] = make_float4(fv[0], fv[1], fv[2], fv[3]);
    }
}

// ---------------------------------------------------------------------------
extern "C" void kernel_launch(void* const* d_in, const int* in_sizes, int n_in,
                              void* d_out, int out_size)
{
    const float* x    = (const float*)d_in[0];
    const float* h    = (const float*)d_in[1];
    const float* c    = (const float*)d_in[2];
    const float* W_hi = (const float*)d_in[3];
    const float* W_xi = (const float*)d_in[4];
    const float* b_i  = (const float*)d_in[5];
    const float* W_hc = (const float*)d_in[6];
    const float* W_xc = (const float*)d_in[7];
    const float* b_c  = (const float*)d_in[8];
    const float* W_ho = (const float*)d_in[9];
    const float* W_xo = (const float*)d_in[10];
    const float* b_o  = (const float*)d_in[11];
    const float* W1   = (const float*)d_in[12];
    const float* b1   = (const float*)d_in[13];
    const float* W2   = (const float*)d_in[14];
    const float* b2   = (const float*)d_in[15];
    const float* W3   = (const float*)d_in[16];
    const float* b3   = (const float*)d_in[17];
    float* out = (float*)d_out;

    cudaFuncSetAttribute(mlp_kernel, cudaFuncAttributeMaxDynamicSharedMemorySize,
                         16 * KTOT * (int)sizeof(float));
    cudaFuncSetAttribute(gemm_hmma, cudaFuncAttributeMaxDynamicSharedMemorySize,
                         SMEM_TOTAL);

    // fork: convA on main stream; convW and mlp on side streams
    cudaEventRecord(g_gs.evRoot, 0);
    cudaStreamWaitEvent(g_gs.sW, g_gs.evRoot, 0);
    cudaStreamWaitEvent(g_gs.sM, g_gs.evRoot, 0);

    convA<<<(BATCH * KTOT / 4) / 256, 256>>>(x, h);
    convW<<<dim3(32, 32, 6), dim3(32, 8), 0, g_gs.sW>>>(W_xi, W_hi, W_xc, W_hc, W_xo, W_ho);
    mlp_kernel<<<256, 256, 16 * KTOT * sizeof(float), g_gs.sM>>>(x, h, W1, b1, W2, b2);

    // gemm needs convA (same stream) + convW (join sW)
    cudaEventRecord(g_gs.evW, g_gs.sW);
    cudaStreamWaitEvent(0, g_gs.evW, 0);

    dim3 grid(HIDSZ / BN, BATCH / BM, 3);   // (8, 128, 3)
    gemm_hmma<<<grid, 256, SMEM_TOTAL>>>(nullptr);

    // epilogue needs gemm (same stream) + mlp (join sM)
    cudaEventRecord(g_gs.evM, g_gs.sM);
    cudaStreamWaitEvent(0, g_gs.evM, 0);

    epilogue<<<BATCH / 8, 256>>>(c, b_i, b_c, b_o, W3, b3, out);
}

// round 11
// speedup vs baseline: 4.2488x; 1.3965x over previous
#include <cuda_runtime.h>
#include <cuda_fp16.h>
#include <cstdint>
#include <math.h>

// -------------------- problem constants --------------------
#define BATCH   8192
#define INSZ    1024
#define HIDSZ   1024
#define KTOT    2048
#define BH      (BATCH * HIDSZ)

// -------------------- GEMM tiling --------------------
#define BM 64
#define BN 128
#define BK 64
#define KITERS (KTOT / BK)          // 32
#define RS 144                      // smem row stride bytes (128B data + 16B pad)
#define TILEA (64 * RS)             // 9216  (A, BM rows)
#define TILEB (128 * RS)            // 18432 (B, BN rows)
#define STAGE_BYTES (TILEA + TILEB) // 27648
#define SMEM_TOTAL (2 * STAGE_BYTES)// 55296  (3 CTAs/SM: 166KB)

// -------------------- device scratch --------------------
__device__ __align__(16) __half gAh[(size_t)BATCH * KTOT];       // A (fp16)
__device__ __align__(16) __half gW [(size_t)3 * HIDSZ * KTOT];   // W^T: [g][n][k]
__device__ __align__(16) float  gP [(size_t)3 * BH];             // pre-activations
__device__ __align__(16) float  g_z2[BATCH * 8];

// -------------------- streams/events for graph fork-join --------------------
namespace {
struct GraphStreams {
    cudaStream_t sW = nullptr, sM = nullptr;
    cudaEvent_t evRoot = nullptr, evW = nullptr, evM = nullptr;
    GraphStreams() {
        cudaStreamCreateWithFlags(&sW, cudaStreamNonBlocking);
        cudaStreamCreateWithFlags(&sM, cudaStreamNonBlocking);
        cudaEventCreateWithFlags(&evRoot, cudaEventDisableTiming);
        cudaEventCreateWithFlags(&evW, cudaEventDisableTiming);
        cudaEventCreateWithFlags(&evM, cudaEventDisableTiming);
    }
};
GraphStreams g_gs;
}

// -------------------- helpers --------------------
__device__ __forceinline__ uint32_t smem_u32(const void* p) {
    uint32_t a;
    asm("{ .reg .u64 t; cvta.to.shared.u64 t, %1; cvt.u32.u64 %0, t; }" : "=r"(a) : "l"(p));
    return a;
}
#define CPASYNC16(dst, src) \
    asm volatile("cp.async.cg.shared.global [%0], [%1], 16;" :: "r"(dst), "l"(src))
#define CP_COMMIT() asm volatile("cp.async.commit_group;")
#define CP_WAIT0()  asm volatile("cp.async.wait_group 0;")

__device__ __forceinline__ void ldmx4(uint32_t addr, uint32_t& r0, uint32_t& r1,
                                      uint32_t& r2, uint32_t& r3) {
    asm volatile("ldmatrix.sync.aligned.m8n8.x4.shared.b16 {%0,%1,%2,%3}, [%4];"
                 : "=r"(r0), "=r"(r1), "=r"(r2), "=r"(r3) : "r"(addr));
}
__device__ __forceinline__ void mma16816(float* d, const uint32_t* a, const uint32_t* b) {
    asm volatile(
        "mma.sync.aligned.m16n8k16.row.col.f32.f16.f16.f32 "
        "{%0,%1,%2,%3}, {%4,%5,%6,%7}, {%8,%9}, {%0,%1,%2,%3};"
        : "+f"(d[0]), "+f"(d[1]), "+f"(d[2]), "+f"(d[3])
        : "r"(a[0]), "r"(a[1]), "r"(a[2]), "r"(a[3]), "r"(b[0]), "r"(b[1]));
}

__device__ __forceinline__ float sigm(float x) { return 1.0f / (1.0f + __expf(-x)); }
__device__ __forceinline__ float tanh_(float x) {
    float t = __expf(2.0f * x);
    return 1.0f - 2.0f / (t + 1.0f);
}

// ---------------------------------------------------------------------------
// convert A = concat(x, h) -> fp16
// ---------------------------------------------------------------------------
__global__ void convA(const float* __restrict__ x, const float* __restrict__ h) {
    int idx = blockIdx.x * blockDim.x + threadIdx.x;   // float4 index
    int row = idx >> 9;                                 // KTOT/4 = 512
    int k   = (idx & 511) * 4;
    float4 v = (k < INSZ)
        ? *(const float4*)(x + (size_t)row * INSZ + k)
        : *(const float4*)(h + (size_t)row * HIDSZ + (k - INSZ));
    size_t o = (size_t)row * KTOT + k;
    __half2* dh = (__half2*)(gAh + o);
    dh[0] = __halves2half2(__float2half_rn(v.x), __float2half_rn(v.y));
    dh[1] = __halves2half2(__float2half_rn(v.z), __float2half_rn(v.w));
}

// ---------------------------------------------------------------------------
// transpose weights: gW[g][n][k] = W[k][n]   (mat = g*2 + half, half0=Wx,1=Wh)
// ---------------------------------------------------------------------------
__global__ void convW(const float* __restrict__ Wxi, const float* __restrict__ Whi,
                      const float* __restrict__ Wxc, const float* __restrict__ Whc,
                      const float* __restrict__ Wxo, const float* __restrict__ Who) {
    __shared__ float t[32][33];
    int mat = blockIdx.z;
    const float* src;
    switch (mat) {
        case 0: src = Wxi; break; case 1: src = Whi; break;
        case 2: src = Wxc; break; case 3: src = Whc; break;
        case 4: src = Wxo; break; default: src = Who; break;
    }
    int n0 = blockIdx.x * 32, k0 = blockIdx.y * 32;
    int tx = threadIdx.x, ty = threadIdx.y;   // 32 x 8
#pragma unroll
    for (int j = 0; j < 4; j++)
        t[ty + j * 8][tx] = src[(size_t)(k0 + ty + j * 8) * HIDSZ + n0 + tx];
    __syncthreads();
    int g = mat >> 1, half = mat & 1;
#pragma unroll
    for (int j = 0; j < 4; j++) {
        int n = n0 + ty + j * 8, k = k0 + tx;
        size_t o = ((size_t)(g * HIDSZ + n)) * KTOT + half * INSZ + k;
        gW[o] = __float2half_rn(t[tx][ty + j * 8]);
    }
}

// ---------------------------------------------------------------------------
// forget-gate MLP front half: z2 = relu(relu(xh@W1+b1)@W2+b2)
// ---------------------------------------------------------------------------
__global__ void mlp_kernel(const float* __restrict__ x, const float* __restrict__ h,
                           const float* __restrict__ W1, const float* __restrict__ b1,
                           const float* __restrict__ W2, const float* __restrict__ b2)
{
    extern __shared__ float sW1T[];   // [16][2048]
    const int tid = threadIdx.x;
    for (int i = tid; i < KTOT * 16; i += blockDim.x) {
        int k = i >> 4, j = i & 15;
        sW1T[j * KTOT + k] = W1[i];
    }
    __syncthreads();

    const int warp = tid >> 5, lane = tid & 31;
    const int gw = blockIdx.x * (blockDim.x >> 5) + warp;
    const int nw = gridDim.x * (blockDim.x >> 5);

    float b1r[16];
#pragma unroll
    for (int j = 0; j < 16; j++) b1r[j] = b1[j];
    float w2r[16];
    float b2r = 0.0f;
    if (lane < 8) {
        b2r = b2[lane];
#pragma unroll
        for (int j = 0; j < 16; j++) w2r[j] = W2[j * 8 + lane];
    }

    for (int row = gw; row < BATCH; row += nw) {
        const float* xr = x + (size_t)row * INSZ;
        const float* hr = h + (size_t)row * HIDSZ;
        float acc[16];
#pragma unroll
        for (int j = 0; j < 16; j++) acc[j] = 0.0f;
#pragma unroll 4
        for (int k = lane; k < KTOT; k += 32) {
            float v = (k < INSZ) ? xr[k] : hr[k - INSZ];
#pragma unroll
            for (int j = 0; j < 16; j++)
                acc[j] = fmaf(v, sW1T[j * KTOT + k], acc[j]);
        }
#pragma unroll
        for (int off = 16; off; off >>= 1) {
#pragma unroll
            for (int j = 0; j < 16; j++)
                acc[j] += __shfl_xor_sync(0xffffffffu, acc[j], off);
        }
        if (lane < 8) {
            float s = b2r;
#pragma unroll
            for (int j = 0; j < 16; j++)
                s = fmaf(fmaxf(acc[j] + b1r[j], 0.0f), w2r[j], s);
            g_z2[row * 8 + lane] = fmaxf(s, 0.0f);
        }
    }
}

// ---------------------------------------------------------------------------
// HMMA GEMM: P[g] = A @ W[g]^T  (single-term fp16)
// grid (n 8, m 128, gate 3), 256 threads, warp grid 2(m) x 4(n), warp tile 32x32
// 3 CTAs/SM
// ---------------------------------------------------------------------------
__global__ __launch_bounds__(256, 3)
void gemm_hmma(float* __restrict__ dummy)
{
    extern __shared__ char smem[];
    const uint32_t sbase = smem_u32(smem);

    const int tid = threadIdx.x;
    const int wid = tid >> 5, lane = tid & 31;
    const int wm = wid & 1, wn = wid >> 1;          // warp coords: 2(m) x 4(n)
    const int g  = blockIdx.z;
    const int m0 = blockIdx.y * BM;
    const int n0 = blockIdx.x * BN;

    const __half* Ah = gAh + (size_t)m0 * KTOT;
    const __half* Bp = gW + ((size_t)g * HIDSZ + n0) * KTOT;

    // staged copy: A (64 rows x 128B) + B (128 rows x 128B)
    auto copy_stage = [&](int kt, int s) {
        const uint32_t base = sbase + s * STAGE_BYTES;
        const int koff = kt * BK;
#pragma unroll
        for (int i = tid; i < 512; i += 256) {
            int row = i >> 3, ch = i & 7;
            uint32_t d = base + row * RS + ch * 16;
            CPASYNC16(d, Ah + (size_t)row * KTOT + koff + ch * 8);
        }
#pragma unroll
        for (int i = tid; i < 1024; i += 256) {
            int row = i >> 3, ch = i & 7;
            uint32_t d = base + TILEA + row * RS + ch * 16;
            CPASYNC16(d, Bp + (size_t)row * KTOT + koff + ch * 8);
        }
    };

    float acc[2][4][4];
#pragma unroll
    for (int mt = 0; mt < 2; mt++)
#pragma unroll
        for (int nt = 0; nt < 4; nt++)
#pragma unroll
            for (int r = 0; r < 4; r++) acc[mt][nt][r] = 0.0f;

    // ldmatrix address components
    const uint32_t aRowOff = (uint32_t)((wm * 32 + (lane & 15)) * RS + ((lane >> 4) & 1) * 16);
    const uint32_t bRowOff = (uint32_t)((wn * 32 + (lane & 7) + ((lane >> 4) & 1) * 8) * RS
                                        + ((lane >> 3) & 1) * 16);

    copy_stage(0, 0);
    CP_COMMIT();

    for (int kt = 0; kt < KITERS; kt++) {
        const int s = kt & 1;
        CP_WAIT0();
        __syncthreads();
        if (kt + 1 < KITERS) { copy_stage(kt + 1, s ^ 1); CP_COMMIT(); }

        const uint32_t base = sbase + s * STAGE_BYTES;
        const uint32_t aB = base + aRowOff;
        const uint32_t bB = base + TILEA + bRowOff;

#pragma unroll
        for (int ks = 0; ks < 4; ks++) {
            const uint32_t kb = (uint32_t)(ks * 32);
            uint32_t b[8];
            ldmx4(bB + kb,            b[0], b[1], b[2], b[3]);   // nt 0,1
            ldmx4(bB + 16 * RS + kb,  b[4], b[5], b[6], b[7]);   // nt 2,3

            uint32_t a[2][4];
#pragma unroll
            for (int mt = 0; mt < 2; mt++)
                ldmx4(aB + mt * 16 * RS + kb, a[mt][0], a[mt][1], a[mt][2], a[mt][3]);
#pragma unroll
            for (int mt = 0; mt < 2; mt++)
#pragma unroll
                for (int nt = 0; nt < 4; nt++)
                    mma16816(acc[mt][nt], a[mt], &b[nt * 2]);
        }
        __syncthreads();
    }

    // write pre-activations
    float* P = gP + (size_t)g * BH;
    const int rbase = m0 + wm * 32 + (lane >> 2);
    const int cbase = n0 + wn * 32 + (lane & 3) * 2;
#pragma unroll
    for (int mt = 0; mt < 2; mt++)
#pragma unroll
        for (int nt = 0; nt < 4; nt++) {
            size_t o0 = (size_t)(rbase + mt * 16) * HIDSZ + cbase + nt * 8;
            *(float2*)&P[o0]             = make_float2(acc[mt][nt][0], acc[mt][nt][1]);
            *(float2*)&P[o0 + 8 * HIDSZ] = make_float2(acc[mt][nt][2], acc[mt][nt][3]);
        }
}

// ---------------------------------------------------------------------------
// epilogue: activations + forget-MLP tail + LSTM update.  8 rows per block.
// ---------------------------------------------------------------------------
__global__ __launch_bounds__(256)
void epilogue(const float* __restrict__ c,
              const float* __restrict__ b_i, const float* __restrict__ b_c,
              const float* __restrict__ b_o,
              const float* __restrict__ W3, const float* __restrict__ b3,
              float* __restrict__ out)
{
    const int r0 = blockIdx.x * 8;
    const int col = threadIdx.x * 4;
    __shared__ float z2s[8][8];
    if (threadIdx.x < 64)
        z2s[threadIdx.x >> 3][threadIdx.x & 7] =
            g_z2[(r0 + (threadIdx.x >> 3)) * 8 + (threadIdx.x & 7)];
    __syncthreads();

    float4 bi = *(const float4*)&b_i[col];
    float4 bc = *(const float4*)&b_c[col];
    float4 bo = *(const float4*)&b_o[col];
    float4 b3v = *(const float4*)&b3[col];
    float4 w3[8];
#pragma unroll
    for (int q = 0; q < 8; q++) w3[q] = *(const float4*)&W3[q * HIDSZ + col];

#pragma unroll 1
    for (int rr = 0; rr < 8; rr++) {
        const int row = r0 + rr;
        const size_t base = (size_t)row * HIDSZ + col;
        float4 pi = *(const float4*)&gP[base];
        float4 pc = *(const float4*)&gP[BH + base];
        float4 po = *(const float4*)&gP[2 * (size_t)BH + base];
        float4 cv = *(const float4*)&c[base];
        float piA[4] = {pi.x, pi.y, pi.z, pi.w};
        float pcA[4] = {pc.x, pc.y, pc.z, pc.w};
        float poA[4] = {po.x, po.y, po.z, po.w};
        float cA[4]  = {cv.x, cv.y, cv.z, cv.w};
        float biA[4] = {bi.x, bi.y, bi.z, bi.w};
        float bcA[4] = {bc.x, bc.y, bc.z, bc.w};
        float boA[4] = {bo.x, bo.y, bo.z, bo.w};
        float b3A[4] = {b3v.x, b3v.y, b3v.z, b3v.w};

        float hn[4], cn[4], fv[4];
#pragma unroll
        for (int j = 0; j < 4; j++) {
            float ii = sigm(piA[j] + biA[j]);
            float gg = tanh_(pcA[j] + bcA[j]);
            float oo = sigm(poA[j] + boA[j]);
            float sf = b3A[j];
#pragma unroll
            for (int q = 0; q < 8; q++) {
                const float* wq = (const float*)&w3[q];
                sf = fmaf(z2s[rr][q], wq[j], sf);
            }
            float ff = sigm(sf);
            float cN = fmaf(ff, cA[j], ii * gg);
            hn[j] = oo * tanh_(cN);
            cn[j] = cN;
            fv[j] = ff;
        }
        *(float4*)&out[base]              = make_float4(hn[0], hn[1], hn[2], hn[3]);
        *(float4*)&out[BH + base]         = make_float4(cn[0], cn[1], cn[2], cn[3]);
        *(float4*)&out[2 * (size_t)BH + base] = make_float4(fv[0], fv[1], fv[2], fv[3]);
    }
}

// ---------------------------------------------------------------------------
extern "C" void kernel_launch(void* const* d_in, const int* in_sizes, int n_in,
                              void* d_out, int out_size)
{
    const float* x    = (const float*)d_in[0];
    const float* h    = (const float*)d_in[1];
    const float* c    = (const float*)d_in[2];
    const float* W_hi = (const float*)d_in[3];
    const float* W_xi = (const float*)d_in[4];
    const float* b_i  = (const float*)d_in[5];
    const float* W_hc = (const float*)d_in[6];
    const float* W_xc = (const float*)d_in[7];
    const float* b_c  = (const float*)d_in[8];
    const float* W_ho = (const float*)d_in[9];
    const float* W_xo = (const float*)d_in[10];
    const float* b_o  = (const float*)d_in[11];
    const float* W1   = (const float*)d_in[12];
    const float* b1   = (const float*)d_in[13];
    const float* W2   = (const float*)d_in[14];
    const float* b2   = (const float*)d_in[15];
    const float* W3   = (const float*)d_in[16];
    const float* b3   = (const float*)d_in[17];
    float* out = (float*)d_out;

    cudaFuncSetAttribute(mlp_kernel, cudaFuncAttributeMaxDynamicSharedMemorySize,
                         16 * KTOT * (int)sizeof(float));
    cudaFuncSetAttribute(gemm_hmma, cudaFuncAttributeMaxDynamicSharedMemorySize,
                         SMEM_TOTAL);

    // fork: convA on main stream; convW and mlp on side streams
    cudaEventRecord(g_gs.evRoot, 0);
    cudaStreamWaitEvent(g_gs.sW, g_gs.evRoot, 0);
    cudaStreamWaitEvent(g_gs.sM, g_gs.evRoot, 0);

    convA<<<(BATCH * KTOT / 4) / 256, 256>>>(x, h);
    convW<<<dim3(32, 32, 6), dim3(32, 8), 0, g_gs.sW>>>(W_xi, W_hi, W_xc, W_hc, W_xo, W_ho);
    mlp_kernel<<<256, 256, 16 * KTOT * sizeof(float), g_gs.sM>>>(x, h, W1, b1, W2, b2);

    // gemm needs convA (same stream) + convW (join sW)
    cudaEventRecord(g_gs.evW, g_gs.sW);
    cudaStreamWaitEvent(0, g_gs.evW, 0);

    dim3 grid(HIDSZ / BN, BATCH / BM, 3);   // (8, 128, 3)
    gemm_hmma<<<grid, 256, SMEM_TOTAL>>>(nullptr);

    // epilogue needs gemm (same stream) + mlp (join sM)
    cudaEventRecord(g_gs.evM, g_gs.sM);
    cudaStreamWaitEvent(0, g_gs.evM, 0);

    epilogue<<<BATCH / 8, 256>>>(c, b_i, b_c, b_o, W3, b3, out);
}

// round 12
// speedup vs baseline: 4.2823x; 1.0079x over previous
#include <cuda_runtime.h>
#include <cuda_fp16.h>
#include <cstdint>
#include <math.h>

// -------------------- problem constants --------------------
#define BATCH   8192
#define INSZ    1024
#define HIDSZ   1024
#define KTOT    2048
#define BH      (BATCH * HIDSZ)

// -------------------- GEMM tiling --------------------
#define BM 64
#define BN 64
#define BK 64
#define KITERS (KTOT / BK)          // 32
#define RS 144                      // smem row stride bytes (128B data + 16B pad)
#define TILEA (64 * RS)             // 9216 (A, BM rows)
#define TILEB (64 * RS)             // 9216 (one gate's B, BN rows)
#define STAGE_BYTES (TILEA + 3 * TILEB)   // 36864
#define SMEM_TOTAL (2 * STAGE_BYTES)      // 73728

// -------------------- device scratch --------------------
__device__ __align__(16) __half gAh[(size_t)BATCH * KTOT];       // A (fp16)
__device__ __align__(16) __half gW [(size_t)3 * HIDSZ * KTOT];   // W^T: [g][n][k]
__device__ __align__(16) float  g_z2[BATCH * 8];

// -------------------- streams/events for graph fork-join --------------------
namespace {
struct GraphStreams {
    cudaStream_t sW = nullptr, sM = nullptr;
    cudaEvent_t evRoot = nullptr, evW = nullptr, evM = nullptr;
    GraphStreams() {
        cudaStreamCreateWithFlags(&sW, cudaStreamNonBlocking);
        cudaStreamCreateWithFlags(&sM, cudaStreamNonBlocking);
        cudaEventCreateWithFlags(&evRoot, cudaEventDisableTiming);
        cudaEventCreateWithFlags(&evW, cudaEventDisableTiming);
        cudaEventCreateWithFlags(&evM, cudaEventDisableTiming);
    }
};
GraphStreams g_gs;
}

// -------------------- helpers --------------------
__device__ __forceinline__ uint32_t smem_u32(const void* p) {
    uint32_t a;
    asm("{ .reg .u64 t; cvta.to.shared.u64 t, %1; cvt.u32.u64 %0, t; }" : "=r"(a) : "l"(p));
    return a;
}
#define CPASYNC16(dst, src) \
    asm volatile("cp.async.cg.shared.global [%0], [%1], 16;" :: "r"(dst), "l"(src))
#define CP_COMMIT() asm volatile("cp.async.commit_group;")
#define CP_WAIT0()  asm volatile("cp.async.wait_group 0;")

__device__ __forceinline__ void ldmx4(uint32_t addr, uint32_t& r0, uint32_t& r1,
                                      uint32_t& r2, uint32_t& r3) {
    asm volatile("ldmatrix.sync.aligned.m8n8.x4.shared.b16 {%0,%1,%2,%3}, [%4];"
                 : "=r"(r0), "=r"(r1), "=r"(r2), "=r"(r3) : "r"(addr));
}
__device__ __forceinline__ void mma16816(float* d, const uint32_t* a, const uint32_t* b) {
    asm volatile(
        "mma.sync.aligned.m16n8k16.row.col.f32.f16.f16.f32 "
        "{%0,%1,%2,%3}, {%4,%5,%6,%7}, {%8,%9}, {%0,%1,%2,%3};"
        : "+f"(d[0]), "+f"(d[1]), "+f"(d[2]), "+f"(d[3])
        : "r"(a[0]), "r"(a[1]), "r"(a[2]), "r"(a[3]), "r"(b[0]), "r"(b[1]));
}

__device__ __forceinline__ float sigm(float x) { return 1.0f / (1.0f + __expf(-x)); }
__device__ __forceinline__ float tanh_(float x) {
    float t = __expf(2.0f * x);
    return 1.0f - 2.0f / (t + 1.0f);
}

// ---------------------------------------------------------------------------
// convert A = concat(x, h) -> fp16
// ---------------------------------------------------------------------------
__global__ void convA(const float* __restrict__ x, const float* __restrict__ h) {
    int idx = blockIdx.x * blockDim.x + threadIdx.x;   // float4 index
    int row = idx >> 9;                                 // KTOT/4 = 512
    int k   = (idx & 511) * 4;
    float4 v = (k < INSZ)
        ? *(const float4*)(x + (size_t)row * INSZ + k)
        : *(const float4*)(h + (size_t)row * HIDSZ + (k - INSZ));
    size_t o = (size_t)row * KTOT + k;
    __half2* dh = (__half2*)(gAh + o);
    dh[0] = __halves2half2(__float2half_rn(v.x), __float2half_rn(v.y));
    dh[1] = __halves2half2(__float2half_rn(v.z), __float2half_rn(v.w));
}

// ---------------------------------------------------------------------------
// transpose weights: gW[g][n][k] = W[k][n]   (mat = g*2 + half, half0=Wx,1=Wh)
// ---------------------------------------------------------------------------
__global__ void convW(const float* __restrict__ Wxi, const float* __restrict__ Whi,
                      const float* __restrict__ Wxc, const float* __restrict__ Whc,
                      const float* __restrict__ Wxo, const float* __restrict__ Who) {
    __shared__ float t[32][33];
    int mat = blockIdx.z;
    const float* src;
    switch (mat) {
        case 0: src = Wxi; break; case 1: src = Whi; break;
        case 2: src = Wxc; break; case 3: src = Whc; break;
        case 4: src = Wxo; break; default: src = Who; break;
    }
    int n0 = blockIdx.x * 32, k0 = blockIdx.y * 32;
    int tx = threadIdx.x, ty = threadIdx.y;   // 32 x 8
#pragma unroll
    for (int j = 0; j < 4; j++)
        t[ty + j * 8][tx] = src[(size_t)(k0 + ty + j * 8) * HIDSZ + n0 + tx];
    __syncthreads();
    int g = mat >> 1, half = mat & 1;
#pragma unroll
    for (int j = 0; j < 4; j++) {
        int n = n0 + ty + j * 8, k = k0 + tx;
        size_t o = ((size_t)(g * HIDSZ + n)) * KTOT + half * INSZ + k;
        gW[o] = __float2half_rn(t[tx][ty + j * 8]);
    }
}

// ---------------------------------------------------------------------------
// forget-gate MLP front half: z2 = relu(relu(xh@W1+b1)@W2+b2)
// ---------------------------------------------------------------------------
__global__ void mlp_kernel(const float* __restrict__ x, const float* __restrict__ h,
                           const float* __restrict__ W1, const float* __restrict__ b1,
                           const float* __restrict__ W2, const float* __restrict__ b2)
{
    extern __shared__ float sW1T[];   // [16][2048]
    const int tid = threadIdx.x;
    for (int i = tid; i < KTOT * 16; i += blockDim.x) {
        int k = i >> 4, j = i & 15;
        sW1T[j * KTOT + k] = W1[i];
    }
    __syncthreads();

    const int warp = tid >> 5, lane = tid & 31;
    const int gw = blockIdx.x * (blockDim.x >> 5) + warp;
    const int nw = gridDim.x * (blockDim.x >> 5);

    float b1r[16];
#pragma unroll
    for (int j = 0; j < 16; j++) b1r[j] = b1[j];
    float w2r[16];
    float b2r = 0.0f;
    if (lane < 8) {
        b2r = b2[lane];
#pragma unroll
        for (int j = 0; j < 16; j++) w2r[j] = W2[j * 8 + lane];
    }

    for (int row = gw; row < BATCH; row += nw) {
        const float* xr = x + (size_t)row * INSZ;
        const float* hr = h + (size_t)row * HIDSZ;
        float acc[16];
#pragma unroll
        for (int j = 0; j < 16; j++) acc[j] = 0.0f;
#pragma unroll 4
        for (int k = lane; k < KTOT; k += 32) {
            float v = (k < INSZ) ? xr[k] : hr[k - INSZ];
#pragma unroll
            for (int j = 0; j < 16; j++)
                acc[j] = fmaf(v, sW1T[j * KTOT + k], acc[j]);
        }
#pragma unroll
        for (int off = 16; off; off >>= 1) {
#pragma unroll
            for (int j = 0; j < 16; j++)
                acc[j] += __shfl_xor_sync(0xffffffffu, acc[j], off);
        }
        if (lane < 8) {
            float s = b2r;
#pragma unroll
            for (int j = 0; j < 16; j++)
                s = fmaf(fmaxf(acc[j] + b1r[j], 0.0f), w2r[j], s);
            g_z2[row * 8 + lane] = fmaxf(s, 0.0f);
        }
    }
}

// ---------------------------------------------------------------------------
// Fused HMMA GEMM + LSTM epilogue.
// Each CTA: 64x64 tile, ALL 3 gates (A staged once, 3 B tiles), then applies
// activations + forget-MLP tail + cell update in-register and writes out.
// grid (n 16, m 128), 256 threads, warp grid 2(m) x 4(n), warp tile 32x16/gate
// ---------------------------------------------------------------------------
__global__ __launch_bounds__(256, 2)
void gemm_fused(const float* __restrict__ c,
                const float* __restrict__ b_i, const float* __restrict__ b_c,
                const float* __restrict__ b_o,
                const float* __restrict__ W3, const float* __restrict__ b3,
                float* __restrict__ out)
{
    extern __shared__ char smem[];
    const uint32_t sbase = smem_u32(smem);

    const int tid = threadIdx.x;
    const int wid = tid >> 5, lane = tid & 31;
    const int wm = wid & 1, wn = wid >> 1;          // warp coords: 2(m) x 4(n)
    const int m0 = blockIdx.y * BM;
    const int n0 = blockIdx.x * BN;

    const __half* Ah = gAh + (size_t)m0 * KTOT;
    const __half* Bp = gW + (size_t)n0 * KTOT;       // gate g at + g*HIDSZ*KTOT

    auto copy_stage = [&](int kt, int s) {
        const uint32_t base = sbase + s * STAGE_BYTES;
        const int koff = kt * BK;
#pragma unroll
        for (int i = tid; i < 512; i += 256) {
            int row = i >> 3, ch = i & 7;
            uint32_t d = base + row * RS + ch * 16;
            const size_t go = (size_t)row * KTOT + koff + ch * 8;
            CPASYNC16(d, Ah + go);
#pragma unroll
            for (int g = 0; g < 3; g++)
                CPASYNC16(d + TILEA + g * TILEB, Bp + (size_t)g * HIDSZ * KTOT + go);
        }
    };

    float acc[3][2][2][4];
#pragma unroll
    for (int g = 0; g < 3; g++)
#pragma unroll
        for (int mt = 0; mt < 2; mt++)
#pragma unroll
            for (int nt = 0; nt < 2; nt++)
#pragma unroll
                for (int r = 0; r < 4; r++) acc[g][mt][nt][r] = 0.0f;

    // ldmatrix address components
    // A: rows = wm*32 + mt*16 + (lane&15); col16 = ((lane>>4)&1)*16
    const uint32_t aRowOff = (uint32_t)((wm * 32 + (lane & 15)) * RS + ((lane >> 4) & 1) * 16);
    // B: rows = wn*16 + (lane&7) + ((lane>>4)&1)*8; col16 = ((lane>>3)&1)*16
    const uint32_t bRowOff = (uint32_t)((wn * 16 + (lane & 7) + ((lane >> 4) & 1) * 8) * RS
                                        + ((lane >> 3) & 1) * 16);

    copy_stage(0, 0);
    CP_COMMIT();

    for (int kt = 0; kt < KITERS; kt++) {
        const int s = kt & 1;
        CP_WAIT0();
        __syncthreads();
        if (kt + 1 < KITERS) { copy_stage(kt + 1, s ^ 1); CP_COMMIT(); }

        const uint32_t base = sbase + s * STAGE_BYTES;
        const uint32_t aB = base + aRowOff;
        const uint32_t bB = base + TILEA + bRowOff;

#pragma unroll
        for (int ks = 0; ks < 4; ks++) {
            const uint32_t kb = (uint32_t)(ks * 32);
            uint32_t a[2][4];
#pragma unroll
            for (int mt = 0; mt < 2; mt++)
                ldmx4(aB + mt * 16 * RS + kb, a[mt][0], a[mt][1], a[mt][2], a[mt][3]);
#pragma unroll
            for (int g = 0; g < 3; g++) {
                uint32_t b[4];
                ldmx4(bB + g * TILEB + kb, b[0], b[1], b[2], b[3]);   // nt 0,1
#pragma unroll
                for (int mt = 0; mt < 2; mt++)
#pragma unroll
                    for (int nt = 0; nt < 2; nt++)
                        mma16816(acc[g][mt][nt], a[mt], &b[nt * 2]);
            }
        }
        __syncthreads();
    }

    // -------------------- fused epilogue --------------------
    __syncthreads();           // all warps done reading stage smem
    float* sp = (float*)smem;  // bi[64] bc[64] bo[64] b3[64] W3[8][64] z2[64][8]
    if (tid < 64) {
        sp[tid]       = b_i[n0 + tid];
        sp[64 + tid]  = b_c[n0 + tid];
        sp[128 + tid] = b_o[n0 + tid];
        sp[192 + tid] = b3[n0 + tid];
    }
    for (int i = tid; i < 512; i += 256) {
        int q = i >> 6, j = i & 63;
        sp[256 + i] = W3[q * HIDSZ + n0 + j];
    }
    if (tid < 128)
        ((float4*)(sp + 768))[tid] = ((const float4*)(g_z2 + (size_t)m0 * 8))[tid];
    __syncthreads();

    const int lr = (lane >> 2);           // 0..7
    const int lc = (lane & 3) * 2;        // 0,2,4,6
#pragma unroll
    for (int mt = 0; mt < 2; mt++)
#pragma unroll
        for (int rr = 0; rr < 2; rr++) {
            const int lrow = wm * 32 + mt * 16 + rr * 8 + lr;     // 0..63
            const int grow = m0 + lrow;
            const float* z2p = sp + 768 + lrow * 8;
#pragma unroll
            for (int nt = 0; nt < 2; nt++) {
                const int lcol = wn * 16 + nt * 8 + lc;           // 0..63
                const size_t o = (size_t)grow * HIDSZ + n0 + lcol;
                float2 cv = *(const float2*)&c[o];
                float hn[2], cn[2], fv[2];
#pragma unroll
                for (int j = 0; j < 2; j++) {
                    const int col = lcol + j;
                    float pre = acc[0][mt][nt][rr * 2 + j];
                    float ii = sigm(pre + sp[col]);
                    float gg = tanh_(acc[1][mt][nt][rr * 2 + j] + sp[64 + col]);
                    float oo = sigm(acc[2][mt][nt][rr * 2 + j] + sp[128 + col]);
                    float sf = sp[192 + col];
#pragma unroll
                    for (int q = 0; q < 8; q++)
                        sf = fmaf(z2p[q], sp[256 + q * 64 + col], sf);
                    float ff = sigm(sf);
                    float cN = fmaf(ff, (j ? cv.y : cv.x), ii * gg);
                    hn[j] = oo * tanh_(cN);
                    cn[j] = cN;
                    fv[j] = ff;
                }
                *(float2*)&out[o]          = make_float2(hn[0], hn[1]);
                *(float2*)&out[BH + o]     = make_float2(cn[0], cn[1]);
                *(float2*)&out[2 * (size_t)BH + o] = make_float2(fv[0], fv[1]);
            }
        }
}

// ---------------------------------------------------------------------------
extern "C" void kernel_launch(void* const* d_in, const int* in_sizes, int n_in,
                              void* d_out, int out_size)
{
    const float* x    = (const float*)d_in[0];
    const float* h    = (const float*)d_in[1];
    const float* c    = (const float*)d_in[2];
    const float* W_hi = (const float*)d_in[3];
    const float* W_xi = (const float*)d_in[4];
    const float* b_i  = (const float*)d_in[5];
    const float* W_hc = (const float*)d_in[6];
    const float* W_xc = (const float*)d_in[7];
    const float* b_c  = (const float*)d_in[8];
    const float* W_ho = (const float*)d_in[9];
    const float* W_xo = (const float*)d_in[10];
    const float* b_o  = (const float*)d_in[11];
    const float* W1   = (const float*)d_in[12];
    const float* b1   = (const float*)d_in[13];
    const float* W2   = (const float*)d_in[14];
    const float* b2   = (const float*)d_in[15];
    const float* W3   = (const float*)d_in[16];
    const float* b3   = (const float*)d_in[17];
    float* out = (float*)d_out;

    cudaFuncSetAttribute(mlp_kernel, cudaFuncAttributeMaxDynamicSharedMemorySize,
                         16 * KTOT * (int)sizeof(float));
    cudaFuncSetAttribute(gemm_fused, cudaFuncAttributeMaxDynamicSharedMemorySize,
                         SMEM_TOTAL);

    // fork: convA on main stream; convW and mlp on side streams
    cudaEventRecord(g_gs.evRoot, 0);
    cudaStreamWaitEvent(g_gs.sW, g_gs.evRoot, 0);
    cudaStreamWaitEvent(g_gs.sM, g_gs.evRoot, 0);

    convA<<<(BATCH * KTOT / 4) / 256, 256>>>(x, h);
    convW<<<dim3(32, 32, 6), dim3(32, 8), 0, g_gs.sW>>>(W_xi, W_hi, W_xc, W_hc, W_xo, W_ho);
    mlp_kernel<<<256, 256, 16 * KTOT * sizeof(float), g_gs.sM>>>(x, h, W1, b1, W2, b2);

    // fused gemm needs convA (same stream) + convW + mlp (joins)
    cudaEventRecord(g_gs.evW, g_gs.sW);
    cudaEventRecord(g_gs.evM, g_gs.sM);
    cudaStreamWaitEvent(0, g_gs.evW, 0);
    cudaStreamWaitEvent(0, g_gs.evM, 0);

    dim3 grid(HIDSZ / BN, BATCH / BM);   // (16, 128)
    gemm_fused<<<grid, 256, SMEM_TOTAL>>>(c, b_i, b_c, b_o, W3, b3, out);
}

// round 13
// speedup vs baseline: 4.2984x; 1.0038x over previous
#include <cuda_runtime.h>
#include <cuda_fp16.h>
#include <cstdint>
#include <math.h>

// -------------------- problem constants --------------------
#define BATCH   8192
#define INSZ    1024
#define HIDSZ   1024
#define KTOT    2048
#define BH      (BATCH * HIDSZ)

// -------------------- GEMM tiling --------------------
#define BM 64
#define BN 64
#define BK 64
#define KITERS (KTOT / BK)          // 32
#define RS 144                      // smem row stride bytes (128B data + 16B pad)
#define TILEA (64 * RS)             // 9216 (A, BM rows)
#define TILEB (64 * RS)             // 9216 (one gate's B, BN rows)
#define STAGE_BYTES (TILEA + 3 * TILEB)   // 36864
#define NSTAGE 3
#define SMEM_TOTAL (NSTAGE * STAGE_BYTES) // 110592 (2 CTAs/SM: 221KB)

// -------------------- device scratch --------------------
__device__ __align__(16) __half gAh[(size_t)BATCH * KTOT];       // A (fp16)
__device__ __align__(16) __half gW [(size_t)3 * HIDSZ * KTOT];   // W^T: [g][n][k]
__device__ __align__(16) float  g_z2[BATCH * 8];

// -------------------- streams/events for graph fork-join --------------------
namespace {
struct GraphStreams {
    cudaStream_t sW = nullptr, sM = nullptr;
    cudaEvent_t evRoot = nullptr, evW = nullptr, evM = nullptr;
    GraphStreams() {
        cudaStreamCreateWithFlags(&sW, cudaStreamNonBlocking);
        cudaStreamCreateWithFlags(&sM, cudaStreamNonBlocking);
        cudaEventCreateWithFlags(&evRoot, cudaEventDisableTiming);
        cudaEventCreateWithFlags(&evW, cudaEventDisableTiming);
        cudaEventCreateWithFlags(&evM, cudaEventDisableTiming);
    }
};
GraphStreams g_gs;
}

// -------------------- helpers --------------------
__device__ __forceinline__ uint32_t smem_u32(const void* p) {
    uint32_t a;
    asm("{ .reg .u64 t; cvta.to.shared.u64 t, %1; cvt.u32.u64 %0, t; }" : "=r"(a) : "l"(p));
    return a;
}
#define CPASYNC16(dst, src) \
    asm volatile("cp.async.cg.shared.global [%0], [%1], 16;" :: "r"(dst), "l"(src))
#define CP_COMMIT() asm volatile("cp.async.commit_group;")
#define CP_WAIT0()  asm volatile("cp.async.wait_group 0;")
#define CP_WAIT1()  asm volatile("cp.async.wait_group 1;")

__device__ __forceinline__ void ldmx4(uint32_t addr, uint32_t& r0, uint32_t& r1,
                                      uint32_t& r2, uint32_t& r3) {
    asm volatile("ldmatrix.sync.aligned.m8n8.x4.shared.b16 {%0,%1,%2,%3}, [%4];"
                 : "=r"(r0), "=r"(r1), "=r"(r2), "=r"(r3) : "r"(addr));
}
__device__ __forceinline__ void mma16816(float* d, const uint32_t* a, const uint32_t* b) {
    asm volatile(
        "mma.sync.aligned.m16n8k16.row.col.f32.f16.f16.f32 "
        "{%0,%1,%2,%3}, {%4,%5,%6,%7}, {%8,%9}, {%0,%1,%2,%3};"
        : "+f"(d[0]), "+f"(d[1]), "+f"(d[2]), "+f"(d[3])
        : "r"(a[0]), "r"(a[1]), "r"(a[2]), "r"(a[3]), "r"(b[0]), "r"(b[1]));
}

__device__ __forceinline__ float sigm(float x) { return 1.0f / (1.0f + __expf(-x)); }
__device__ __forceinline__ float tanh_(float x) {
    float t = __expf(2.0f * x);
    return 1.0f - 2.0f / (t + 1.0f);
}

// ---------------------------------------------------------------------------
// convert A = concat(x, h) -> fp16
// ---------------------------------------------------------------------------
__global__ void convA(const float* __restrict__ x, const float* __restrict__ h) {
    int idx = blockIdx.x * blockDim.x + threadIdx.x;   // float4 index
    int row = idx >> 9;                                 // KTOT/4 = 512
    int k   = (idx & 511) * 4;
    float4 v = (k < INSZ)
        ? *(const float4*)(x + (size_t)row * INSZ + k)
        : *(const float4*)(h + (size_t)row * HIDSZ + (k - INSZ));
    size_t o = (size_t)row * KTOT + k;
    __half2* dh = (__half2*)(gAh + o);
    dh[0] = __halves2half2(__float2half_rn(v.x), __float2half_rn(v.y));
    dh[1] = __halves2half2(__float2half_rn(v.z), __float2half_rn(v.w));
}

// ---------------------------------------------------------------------------
// transpose weights: gW[g][n][k] = W[k][n]   (mat = g*2 + half, half0=Wx,1=Wh)
// ---------------------------------------------------------------------------
__global__ void convW(const float* __restrict__ Wxi, const float* __restrict__ Whi,
                      const float* __restrict__ Wxc, const float* __restrict__ Whc,
                      const float* __restrict__ Wxo, const float* __restrict__ Who) {
    __shared__ float t[32][33];
    int mat = blockIdx.z;
    const float* src;
    switch (mat) {
        case 0: src = Wxi; break; case 1: src = Whi; break;
        case 2: src = Wxc; break; case 3: src = Whc; break;
        case 4: src = Wxo; break; default: src = Who; break;
    }
    int n0 = blockIdx.x * 32, k0 = blockIdx.y * 32;
    int tx = threadIdx.x, ty = threadIdx.y;   // 32 x 8
#pragma unroll
    for (int j = 0; j < 4; j++)
        t[ty + j * 8][tx] = src[(size_t)(k0 + ty + j * 8) * HIDSZ + n0 + tx];
    __syncthreads();
    int g = mat >> 1, half = mat & 1;
#pragma unroll
    for (int j = 0; j < 4; j++) {
        int n = n0 + ty + j * 8, k = k0 + tx;
        size_t o = ((size_t)(g * HIDSZ + n)) * KTOT + half * INSZ + k;
        gW[o] = __float2half_rn(t[tx][ty + j * 8]);
    }
}

// ---------------------------------------------------------------------------
// forget-gate MLP front half: z2 = relu(relu(xh@W1+b1)@W2+b2)
// ---------------------------------------------------------------------------
__global__ void mlp_kernel(const float* __restrict__ x, const float* __restrict__ h,
                           const float* __restrict__ W1, const float* __restrict__ b1,
                           const float* __restrict__ W2, const float* __restrict__ b2)
{
    extern __shared__ float sW1T[];   // [16][2048]
    const int tid = threadIdx.x;
    for (int i = tid; i < KTOT * 16; i += blockDim.x) {
        int k = i >> 4, j = i & 15;
        sW1T[j * KTOT + k] = W1[i];
    }
    __syncthreads();

    const int warp = tid >> 5, lane = tid & 31;
    const int gw = blockIdx.x * (blockDim.x >> 5) + warp;
    const int nw = gridDim.x * (blockDim.x >> 5);

    float b1r[16];
#pragma unroll
    for (int j = 0; j < 16; j++) b1r[j] = b1[j];
    float w2r[16];
    float b2r = 0.0f;
    if (lane < 8) {
        b2r = b2[lane];
#pragma unroll
        for (int j = 0; j < 16; j++) w2r[j] = W2[j * 8 + lane];
    }

    for (int row = gw; row < BATCH; row += nw) {
        const float* xr = x + (size_t)row * INSZ;
        const float* hr = h + (size_t)row * HIDSZ;
        float acc[16];
#pragma unroll
        for (int j = 0; j < 16; j++) acc[j] = 0.0f;
#pragma unroll 4
        for (int k = lane; k < KTOT; k += 32) {
            float v = (k < INSZ) ? xr[k] : hr[k - INSZ];
#pragma unroll
            for (int j = 0; j < 16; j++)
                acc[j] = fmaf(v, sW1T[j * KTOT + k], acc[j]);
        }
#pragma unroll
        for (int off = 16; off; off >>= 1) {
#pragma unroll
            for (int j = 0; j < 16; j++)
                acc[j] += __shfl_xor_sync(0xffffffffu, acc[j], off);
        }
        if (lane < 8) {
            float s = b2r;
#pragma unroll
            for (int j = 0; j < 16; j++)
                s = fmaf(fmaxf(acc[j] + b1r[j], 0.0f), w2r[j], s);
            g_z2[row * 8 + lane] = fmaxf(s, 0.0f);
        }
    }
}

// ---------------------------------------------------------------------------
// Fused HMMA GEMM + LSTM epilogue, 3-stage cp.async pipeline.
// Each CTA: 64x64 tile, ALL 3 gates, epilogue in-register, writes out.
// grid (n 16, m 128), 256 threads, warp grid 2(m) x 4(n)
// ---------------------------------------------------------------------------
__global__ __launch_bounds__(256, 2)
void gemm_fused(const float* __restrict__ c,
                const float* __restrict__ b_i, const float* __restrict__ b_c,
                const float* __restrict__ b_o,
                const float* __restrict__ W3, const float* __restrict__ b3,
                float* __restrict__ out)
{
    extern __shared__ char smem[];
    const uint32_t sbase = smem_u32(smem);

    const int tid = threadIdx.x;
    const int wid = tid >> 5, lane = tid & 31;
    const int wm = wid & 1, wn = wid >> 1;          // warp coords: 2(m) x 4(n)
    const int m0 = blockIdx.y * BM;
    const int n0 = blockIdx.x * BN;

    const __half* Ah = gAh + (size_t)m0 * KTOT;
    const __half* Bp = gW + (size_t)n0 * KTOT;       // gate g at + g*HIDSZ*KTOT

    auto copy_stage = [&](int kt, int s) {
        const uint32_t base = sbase + s * STAGE_BYTES;
        const int koff = kt * BK;
#pragma unroll
        for (int i = tid; i < 512; i += 256) {
            int row = i >> 3, ch = i & 7;
            uint32_t d = base + row * RS + ch * 16;
            const size_t go = (size_t)row * KTOT + koff + ch * 8;
            CPASYNC16(d, Ah + go);
#pragma unroll
            for (int g = 0; g < 3; g++)
                CPASYNC16(d + TILEA + g * TILEB, Bp + (size_t)g * HIDSZ * KTOT + go);
        }
    };

    float acc[3][2][2][4];
#pragma unroll
    for (int g = 0; g < 3; g++)
#pragma unroll
        for (int mt = 0; mt < 2; mt++)
#pragma unroll
            for (int nt = 0; nt < 2; nt++)
#pragma unroll
                for (int r = 0; r < 4; r++) acc[g][mt][nt][r] = 0.0f;

    // ldmatrix address components
    const uint32_t aRowOff = (uint32_t)((wm * 32 + (lane & 15)) * RS + ((lane >> 4) & 1) * 16);
    const uint32_t bRowOff = (uint32_t)((wn * 16 + (lane & 7) + ((lane >> 4) & 1) * 8) * RS
                                        + ((lane >> 3) & 1) * 16);

    copy_stage(0, 0);
    CP_COMMIT();
    copy_stage(1, 1);
    CP_COMMIT();

    int s = 0;
    for (int kt = 0; kt < KITERS; kt++) {
        // oldest pending group is c(kt); allow c(kt+1) to keep streaming
        if (kt + 1 < KITERS) { CP_WAIT1(); } else { CP_WAIT0(); }
        __syncthreads();
        if (kt + 2 < KITERS) {
            int s2 = s + 2; if (s2 >= NSTAGE) s2 -= NSTAGE;
            copy_stage(kt + 2, s2);
            CP_COMMIT();
        }

        const uint32_t base = sbase + s * STAGE_BYTES;
        const uint32_t aB = base + aRowOff;
        const uint32_t bB = base + TILEA + bRowOff;

#pragma unroll
        for (int ks = 0; ks < 4; ks++) {
            const uint32_t kb = (uint32_t)(ks * 32);
            uint32_t a[2][4];
#pragma unroll
            for (int mt = 0; mt < 2; mt++)
                ldmx4(aB + mt * 16 * RS + kb, a[mt][0], a[mt][1], a[mt][2], a[mt][3]);
#pragma unroll
            for (int g = 0; g < 3; g++) {
                uint32_t b[4];
                ldmx4(bB + g * TILEB + kb, b[0], b[1], b[2], b[3]);   // nt 0,1
#pragma unroll
                for (int mt = 0; mt < 2; mt++)
#pragma unroll
                    for (int nt = 0; nt < 2; nt++)
                        mma16816(acc[g][mt][nt], a[mt], &b[nt * 2]);
            }
        }
        if (++s >= NSTAGE) s = 0;
        __syncthreads();
    }

    // -------------------- fused epilogue --------------------
    float* sp = (float*)smem;  // bi[64] bc[64] bo[64] b3[64] W3[8][64] z2[64][8]
    if (tid < 64) {
        sp[tid]       = b_i[n0 + tid];
        sp[64 + tid]  = b_c[n0 + tid];
        sp[128 + tid] = b_o[n0 + tid];
        sp[192 + tid] = b3[n0 + tid];
    }
    for (int i = tid; i < 512; i += 256) {
        int q = i >> 6, j = i & 63;
        sp[256 + i] = W3[q * HIDSZ + n0 + j];
    }
    if (tid < 128)
        ((float4*)(sp + 768))[tid] = ((const float4*)(g_z2 + (size_t)m0 * 8))[tid];
    __syncthreads();

    const int lr = (lane >> 2);           // 0..7
    const int lc = (lane & 3) * 2;        // 0,2,4,6
#pragma unroll
    for (int mt = 0; mt < 2; mt++)
#pragma unroll
        for (int rr = 0; rr < 2; rr++) {
            const int lrow = wm * 32 + mt * 16 + rr * 8 + lr;     // 0..63
            const int grow = m0 + lrow;
            const float* z2p = sp + 768 + lrow * 8;
#pragma unroll
            for (int nt = 0; nt < 2; nt++) {
                const int lcol = wn * 16 + nt * 8 + lc;           // 0..63
                const size_t o = (size_t)grow * HIDSZ + n0 + lcol;
                float2 cv = *(const float2*)&c[o];
                float hn[2], cn[2], fv[2];
#pragma unroll
                for (int j = 0; j < 2; j++) {
                    const int col = lcol + j;
                    float ii = sigm(acc[0][mt][nt][rr * 2 + j] + sp[col]);
                    float gg = tanh_(acc[1][mt][nt][rr * 2 + j] + sp[64 + col]);
                    float oo = sigm(acc[2][mt][nt][rr * 2 + j] + sp[128 + col]);
                    float sf = sp[192 + col];
#pragma unroll
                    for (int q = 0; q < 8; q++)
                        sf = fmaf(z2p[q], sp[256 + q * 64 + col], sf);
                    float ff = sigm(sf);
                    float cN = fmaf(ff, (j ? cv.y : cv.x), ii * gg);
                    hn[j] = oo * tanh_(cN);
                    cn[j] = cN;
                    fv[j] = ff;
                }
                *(float2*)&out[o]          = make_float2(hn[0], hn[1]);
                *(float2*)&out[BH + o]     = make_float2(cn[0], cn[1]);
                *(float2*)&out[2 * (size_t)BH + o] = make_float2(fv[0], fv[1]);
            }
        }
}

// ---------------------------------------------------------------------------
extern "C" void kernel_launch(void* const* d_in, const int* in_sizes, int n_in,
                              void* d_out, int out_size)
{
    const float* x    = (const float*)d_in[0];
    const float* h    = (const float*)d_in[1];
    const float* c    = (const float*)d_in[2];
    const float* W_hi = (const float*)d_in[3];
    const float* W_xi = (const float*)d_in[4];
    const float* b_i  = (const float*)d_in[5];
    const float* W_hc = (const float*)d_in[6];
    const float* W_xc = (const float*)d_in[7];
    const float* b_c  = (const float*)d_in[8];
    const float* W_ho = (const float*)d_in[9];
    const float* W_xo = (const float*)d_in[10];
    const float* b_o  = (const float*)d_in[11];
    const float* W1   = (const float*)d_in[12];
    const float* b1   = (const float*)d_in[13];
    const float* W2   = (const float*)d_in[14];
    const float* b2   = (const float*)d_in[15];
    const float* W3   = (const float*)d_in[16];
    const float* b3   = (const float*)d_in[17];
    float* out = (float*)d_out;

    cudaFuncSetAttribute(mlp_kernel, cudaFuncAttributeMaxDynamicSharedMemorySize,
                         16 * KTOT * (int)sizeof(float));
    cudaFuncSetAttribute(gemm_fused, cudaFuncAttributeMaxDynamicSharedMemorySize,
                         SMEM_TOTAL);

    // fork: convA on main stream; convW and mlp on side streams
    cudaEventRecord(g_gs.evRoot, 0);
    cudaStreamWaitEvent(g_gs.sW, g_gs.evRoot, 0);
    cudaStreamWaitEvent(g_gs.sM, g_gs.evRoot, 0);

    convA<<<(BATCH * KTOT / 4) / 256, 256>>>(x, h);
    convW<<<dim3(32, 32, 6), dim3(32, 8), 0, g_gs.sW>>>(W_xi, W_hi, W_xc, W_hc, W_xo, W_ho);
    mlp_kernel<<<256, 256, 16 * KTOT * sizeof(float), g_gs.sM>>>(x, h, W1, b1, W2, b2);

    // fused gemm needs convA (same stream) + convW + mlp (joins)
    cudaEventRecord(g_gs.evW, g_gs.sW);
    cudaEventRecord(g_gs.evM, g_gs.sM);
    cudaStreamWaitEvent(0, g_gs.evW, 0);
    cudaStreamWaitEvent(0, g_gs.evM, 0);

    dim3 grid(HIDSZ / BN, BATCH / BM);   // (16, 128)
    gemm_fused<<<grid, 256, SMEM_TOTAL>>>(c, b_i, b_c, b_o, W3, b3, out);
}